// round 8
// baseline (speedup 1.0000x reference)
#include <cuda_runtime.h>
#include <math.h>

// ElasticBand (NEB) — flat 2-kernel scheme at the DRAM roofline.
// Kernel R: one block per (interior image, atom chunk); 8 independent loads per
//   thread, block reduce, partial -> L2. The LAST block of each image (atomic
//   ticket) folds all partials and computes the per-image coefficients inline
//   (eng logic recomputed locally; no separate init/scalars kernels).
// Kernel O: flat streaming out = g1*frc + alpha*dp + beta*dm. pos reads dedup
//   in L2 (3x logical -> ~1x DRAM); frc reads + out writes streamed (.cs).

#define KMAXC 0.1f
#define DLTKC 0.02f
#define EPSC  0.1f
#define PI_F  3.14159265358979323846f

#define TA    256                // threads per block
#define KPT   2                  // float4 per thread
#define TILEA (TA * KPT)         // 512 float4 per block
#define MAX_INT 62
#define MAX_NB  1280

__device__ float g_part[(size_t)MAX_INT * MAX_NB * 6];  // [ii][block][6]
__device__ float g_coef[MAX_INT * 4];                    // g1, alpha, beta
__device__ unsigned int g_tick[MAX_INT];                 // per-image arrival tickets

__device__ __forceinline__ float warpSum(float v) {
    #pragma unroll
    for (int o = 16; o > 0; o >>= 1) v += __shfl_xor_sync(0xffffffffu, v, o);
    return v;
}

__device__ __forceinline__ float spring_k(float ea, float eb, float emax, float eref) {
    float k = KMAXC - DLTKC * (emax - fmaxf(ea, eb)) / (emax - eref);
    if (fmaxf(ea, eb) < eref) k = KMAXC - DLTKC;
    return k;
}

// ---- coefficient math: folded sums + inline eng logic -------------------------
__device__ __forceinline__ void coefFromEng(
    const float* S, const float* __restrict__ eng, int n_img, int ii,
    float& g1, float& al, float& be)
{
    const float A = S[0], B = S[1], C = S[2], D = S[3], E = S[4], W = S[5];

    float emin = eng[0], emax = eng[0];
    int imax = 0;
    for (int p = 1; p < n_img; p++) {
        float e = eng[p];
        if (e < emin) emin = e;
        if (e > emax) { emax = e; imax = p; }   // strict > keeps first max
    }
    const float eref = emin - EPSC;

    const int i = ii + 1;
    const float e0 = eng[i - 1], e1 = eng[i], e2 = eng[i + 1];
    const float km = spring_k(e0, e1, emax, eref);
    const float kp = spring_k(e1, e2, emax, eref);

    float cp, cm;
    if (e2 > e1 && e1 > e0)      { cp = 1.f;  cm = 0.f; }
    else if (e2 < e1 && e1 < e0) { cp = 0.f;  cm = 1.f; }
    else {
        float d1 = fabsf(e2 - e1), d0 = fabsf(e0 - e1);
        float dvmax = fmaxf(d1, d0), dvmin = fminf(d1, d0);
        if (e2 > e1)      { cp = dvmax; cm = dvmin; }
        else if (e2 < e1) { cp = dvmin; cm = dvmax; }
        else              { cp = 0.f;   cm = 0.f; }
    }
    const float mu = (ii == imax) ? 2.f : 1.f;   // .at[i_raw] quirk (OOB -> no-op)

    const float Stt = cp * cp * A + 2.f * cp * cm * C + cm * cm * B;
    const float Sft = cp * D + cm * E;
    const float a   = Sft / Stt;
    const float s   = (kp * sqrtf(B) - km * sqrtf(A)) / sqrtf(Stt);

    const float F   = W - Sft * Sft / Stt;
    const float Tm  = cp * C + cm * B;
    const float Tp  = cp * A + cm * C;
    const float St  = kp * Tm - km * Tp;
    const float Gv  = kp * kp * B + km * km * A - 2.f * kp * km * C
                      - 2.f * s * St + s * s * Stt;
    const float Sf  = kp * E - km * D;
    const float H   = Sf - a * St - s * Sft + s * a * Stt;

    const float sw  = (2.0f / PI_F) * atan2f(F, Gv);
    const float Hsw = H * sw;

    g1 = 1.f - Hsw;
    al = a * (Hsw - mu) * cp - km;
    be = a * (Hsw - mu) * cm + kp;
}

// ---- R: flat 2D reduce + last-block fold --------------------------------------
__global__ void __launch_bounds__(TA) nebReduceF(
    const float4* __restrict__ pos4,
    const float4* __restrict__ frc4,
    const float* __restrict__ eng,
    int nvec, int n_img, int nb)
{
    const int ii = blockIdx.x;        // interior index
    const int i  = ii + 1;            // global image
    const int b  = blockIdx.y;        // atom chunk
    const int t  = threadIdx.x;

    float vA = 0.f, vB = 0.f, vC = 0.f, vD = 0.f, vE = 0.f, vW = 0.f;

    #pragma unroll
    for (int k = 0; k < KPT; k++) {
        const int j = b * TILEA + k * TA + t;
        if (j < nvec) {
            const size_t base = (size_t)i * nvec + j;
            float4 pm = pos4[base - nvec];
            float4 pc = pos4[base];
            float4 pp = pos4[base + nvec];
            float4 f  = __ldcs(&frc4[base]);

            float dpx = pc.x - pm.x, dmx = pp.x - pc.x;
            float dpy = pc.y - pm.y, dmy = pp.y - pc.y;
            float dpz = pc.z - pm.z, dmz = pp.z - pc.z;
            float dpw = pc.w - pm.w, dmw = pp.w - pc.w;

            vA = fmaf(dpx, dpx, fmaf(dpy, dpy, fmaf(dpz, dpz, fmaf(dpw, dpw, vA))));
            vB = fmaf(dmx, dmx, fmaf(dmy, dmy, fmaf(dmz, dmz, fmaf(dmw, dmw, vB))));
            vC = fmaf(dpx, dmx, fmaf(dpy, dmy, fmaf(dpz, dmz, fmaf(dpw, dmw, vC))));
            vD = fmaf(f.x, dpx, fmaf(f.y, dpy, fmaf(f.z, dpz, fmaf(f.w, dpw, vD))));
            vE = fmaf(f.x, dmx, fmaf(f.y, dmy, fmaf(f.z, dmz, fmaf(f.w, dmw, vE))));
            vW = fmaf(f.x, f.x, fmaf(f.y, f.y, fmaf(f.z, f.z, fmaf(f.w, f.w, vW))));
        }
    }

    __shared__ float sred[6][TA / 32];
    __shared__ bool  sLast;
    float vals[6] = { vA, vB, vC, vD, vE, vW };
    #pragma unroll
    for (int c = 0; c < 6; c++) {
        float r = warpSum(vals[c]);
        if ((t & 31) == 0) sred[c][t >> 5] = r;
    }
    __syncthreads();
    if (t < 6) {
        float s = 0.f;
        #pragma unroll
        for (int w = 0; w < TA / 32; w++) s += sred[t][w];
        g_part[((size_t)ii * nb + b) * 6 + t] = s;
    }
    // last-block-folds ticket (threadFenceReduction pattern)
    if (t == 0) {
        __threadfence();
        unsigned int v = atomicAdd(&g_tick[ii], 1u);
        sLast = (v == (unsigned int)(nb - 1));
    }
    __syncthreads();
    if (!sLast) return;

    // this block is the last to finish image ii: fold all nb partials
    float acc[6] = {0.f, 0.f, 0.f, 0.f, 0.f, 0.f};
    for (int p = t; p < nb; p += TA) {
        const float* pp = &g_part[((size_t)ii * nb + p) * 6];
        #pragma unroll
        for (int c = 0; c < 6; c++) acc[c] += pp[c];
    }
    #pragma unroll
    for (int c = 0; c < 6; c++) {
        float r = warpSum(acc[c]);
        if ((t & 31) == 0) sred[c][t >> 5] = r;
    }
    __syncthreads();
    if (t == 0) {
        float S[6];
        #pragma unroll
        for (int c = 0; c < 6; c++) {
            float s = 0.f;
            #pragma unroll
            for (int w = 0; w < TA / 32; w++) s += sred[c][w];
            S[c] = s;
        }
        float g1, al, be;
        coefFromEng(S, eng, n_img, ii, g1, al, be);
        g_coef[ii * 4 + 0] = g1;
        g_coef[ii * 4 + 1] = al;
        g_coef[ii * 4 + 2] = be;
        g_tick[ii] = 0u;              // self-reset for next graph replay
    }
}

// ---- O: flat streaming output ---------------------------------------------------
__global__ void nebOut(
    const float4* __restrict__ pos4,
    const float4* __restrict__ frc4,
    float4* __restrict__ out4,
    int nvec, int n_img)
{
    size_t gid = (size_t)blockIdx.x * blockDim.x + threadIdx.x;
    size_t total = (size_t)n_img * nvec;
    if (gid >= total) return;

    int img = (int)(gid / (unsigned)nvec);
    float4 f = __ldcs(&frc4[gid]);

    if (img == 0 || img == n_img - 1) { __stcs(&out4[gid], f); return; }

    const int ii = img - 1;
    const float g1 = __ldg(&g_coef[ii * 4 + 0]);
    const float al = __ldg(&g_coef[ii * 4 + 1]);
    const float be = __ldg(&g_coef[ii * 4 + 2]);

    float4 pm = pos4[gid - nvec];
    float4 pc = pos4[gid];
    float4 pp = pos4[gid + nvec];

    float4 o;
    o.x = fmaf(g1, f.x, fmaf(al, pc.x - pm.x, be * (pp.x - pc.x)));
    o.y = fmaf(g1, f.y, fmaf(al, pc.y - pm.y, be * (pp.y - pc.y)));
    o.z = fmaf(g1, f.z, fmaf(al, pc.z - pm.z, be * (pp.z - pc.z)));
    o.w = fmaf(g1, f.w, fmaf(al, pc.w - pm.w, be * (pp.w - pc.w)));
    __stcs(&out4[gid], o);
}

// =============================================================================
extern "C" void kernel_launch(void* const* d_in, const int* in_sizes, int n_in,
                              void* d_out, int out_size)
{
    const float* pos = (const float*)d_in[0];
    const float* frc = (const float*)d_in[1];
    const float* eng = (const float*)d_in[2];

    const int n_img    = in_sizes[2];                 // 32
    const long per_img = (long)in_sizes[0] / n_img;   // 1,200,000 floats
    const int  nvec    = (int)(per_img / 4);          // 300,000 float4
    const int  n_int   = n_img - 2;

    const float4* pos4 = (const float4*)pos;
    const float4* frc4 = (const float4*)frc;
    float4* out4 = (float4*)d_out;

    const int nb = (nvec + TILEA - 1) / TILEA;        // 586 chunks

    size_t total = (size_t)n_img * nvec;
    int blocksC = (int)((total + 255) / 256);

    if (n_int < 1) {
        nebOut<<<blocksC, 256>>>(pos4, frc4, out4, nvec, n_img);
        return;
    }

    nebReduceF<<<dim3(n_int, nb), TA>>>(pos4, frc4, eng, nvec, n_img, nb);
    nebOut<<<blocksC, 256>>>(pos4, frc4, out4, nvec, n_img);
}

// round 9
// speedup vs baseline: 1.0121x; 1.0121x over previous
#include <cuda_runtime.h>
#include <math.h>

// ElasticBand (NEB) — flat 3-pass scheme + cross-kernel L2 tail reuse.
// Pass R: flat 2D reduce (image, atom band), streams atom axis ASCENDING.
//   At R's end, L2 holds the highest atom bands of pos+frc (all images).
// Pass S: fold 586 block partials per image + eng logic -> (g1, alpha, beta).
// Pass O: flat output run in REVERSE atom order -> its first reads are L2 hits
//   on R's resident tail (~120MB fewer DRAM reads). Out writes use .cs so the
//   write stream doesn't evict the not-yet-consumed hot input lines.

#define KMAXC 0.1f
#define DLTKC 0.02f
#define EPSC  0.1f
#define PI_F  3.14159265358979323846f

#define TA    256                // threads per block
#define KPT   2                  // float4 per thread
#define TILEA (TA * KPT)         // 512 float4 per block
#define MAX_INT 62
#define MAX_NB  1280

__device__ float g_part[(size_t)MAX_INT * MAX_NB * 6];  // [ii][block][6]
__device__ float g_escal[MAX_INT * 6];                   // cp, cm, km, kp, mult
__device__ float g_coef[MAX_INT * 4];                    // g1, alpha, beta

__device__ __forceinline__ float warpSum(float v) {
    #pragma unroll
    for (int o = 16; o > 0; o >>= 1) v += __shfl_xor_sync(0xffffffffu, v, o);
    return v;
}

__device__ __forceinline__ float spring_k(float ea, float eb, float emax, float eref) {
    float ei = fmaxf(ea, eb);
    float k = KMAXC - DLTKC * (emax - ei) / (emax - eref);
    if (ei < eref) k = KMAXC - DLTKC;
    return k;
}

// ---- eng-only precompute (1 tiny block) -------------------------------------
__global__ void nebInit(const float* __restrict__ eng, int n_img)
{
    if (threadIdx.x != 0) return;

    float emin = eng[0], emax = eng[0];
    int imax = 0;
    for (int p = 1; p < n_img; p++) {
        float e = eng[p];
        if (e < emin) emin = e;
        if (e > emax) { emax = e; imax = p; }   // strict > keeps first max
    }
    const float eref = emin - EPSC;
    const int n_int = n_img - 2;

    for (int j = 0; j < n_int; j++) {
        const int i = j + 1;
        const float e0 = eng[i - 1], e1 = eng[i], e2 = eng[i + 1];
        const float km = spring_k(e0, e1, emax, eref);
        const float kp = spring_k(e1, e2, emax, eref);

        float cp, cm;
        if (e2 > e1 && e1 > e0)      { cp = 1.f;  cm = 0.f; }
        else if (e2 < e1 && e1 < e0) { cp = 0.f;  cm = 1.f; }
        else {
            float d1 = fabsf(e2 - e1), d0 = fabsf(e0 - e1);
            float dvmax = fmaxf(d1, d0), dvmin = fminf(d1, d0);
            if (e2 > e1)      { cp = dvmax; cm = dvmin; }
            else if (e2 < e1) { cp = dvmin; cm = dvmax; }
            else              { cp = 0.f;   cm = 0.f; }
        }
        const float mult = (j == imax) ? 2.f : 1.f;  // .at[i_raw] quirk

        g_escal[j * 6 + 0] = cp;
        g_escal[j * 6 + 1] = cm;
        g_escal[j * 6 + 2] = km;
        g_escal[j * 6 + 3] = kp;
        g_escal[j * 6 + 4] = mult;
    }
}

// ---- coefficient math --------------------------------------------------------
__device__ __forceinline__ void coefFrom(
    const float* S, int ii, float& g1, float& al, float& be)
{
    const float A = S[0], B = S[1], C = S[2], D = S[3], E = S[4], W = S[5];
    const float cp = g_escal[ii * 6 + 0];
    const float cm = g_escal[ii * 6 + 1];
    const float km = g_escal[ii * 6 + 2];
    const float kp = g_escal[ii * 6 + 3];
    const float mu = g_escal[ii * 6 + 4];

    const float Stt = cp * cp * A + 2.f * cp * cm * C + cm * cm * B;
    const float Sft = cp * D + cm * E;
    const float a   = Sft / Stt;
    const float s   = (kp * sqrtf(B) - km * sqrtf(A)) / sqrtf(Stt);

    const float F   = W - Sft * Sft / Stt;
    const float Tm  = cp * C + cm * B;
    const float Tp  = cp * A + cm * C;
    const float St  = kp * Tm - km * Tp;
    const float Gv  = kp * kp * B + km * km * A - 2.f * kp * km * C
                      - 2.f * s * St + s * s * Stt;
    const float Sf  = kp * E - km * D;
    const float H   = Sf - a * St - s * Sft + s * a * Stt;

    const float sw  = (2.0f / PI_F) * atan2f(F, Gv);
    const float Hsw = H * sw;

    g1 = 1.f - Hsw;
    al = a * (Hsw - mu) * cp - km;
    be = a * (Hsw - mu) * cm + kp;
}

// ---- R: flat 2D reduce. block = (image ii = blockIdx.x, band b = blockIdx.y) --
__global__ void __launch_bounds__(TA) nebReduceF(
    const float4* __restrict__ pos4,
    const float4* __restrict__ frc4,
    int nvec, int nb)
{
    const int ii = blockIdx.x;        // interior index
    const int i  = ii + 1;            // global image
    const int b  = blockIdx.y;        // atom band (ascending across waves)
    const int t  = threadIdx.x;

    float vA = 0.f, vB = 0.f, vC = 0.f, vD = 0.f, vE = 0.f, vW = 0.f;

    #pragma unroll
    for (int k = 0; k < KPT; k++) {
        const int j = b * TILEA + k * TA + t;
        if (j < nvec) {
            const size_t base = (size_t)i * nvec + j;
            float4 pm = pos4[base - nvec];
            float4 pc = pos4[base];
            float4 pp = pos4[base + nvec];
            float4 f  = frc4[base];

            float dpx = pc.x - pm.x, dmx = pp.x - pc.x;
            float dpy = pc.y - pm.y, dmy = pp.y - pc.y;
            float dpz = pc.z - pm.z, dmz = pp.z - pc.z;
            float dpw = pc.w - pm.w, dmw = pp.w - pc.w;

            vA = fmaf(dpx, dpx, fmaf(dpy, dpy, fmaf(dpz, dpz, fmaf(dpw, dpw, vA))));
            vB = fmaf(dmx, dmx, fmaf(dmy, dmy, fmaf(dmz, dmz, fmaf(dmw, dmw, vB))));
            vC = fmaf(dpx, dmx, fmaf(dpy, dmy, fmaf(dpz, dmz, fmaf(dpw, dmw, vC))));
            vD = fmaf(f.x, dpx, fmaf(f.y, dpy, fmaf(f.z, dpz, fmaf(f.w, dpw, vD))));
            vE = fmaf(f.x, dmx, fmaf(f.y, dmy, fmaf(f.z, dmz, fmaf(f.w, dmw, vE))));
            vW = fmaf(f.x, f.x, fmaf(f.y, f.y, fmaf(f.z, f.z, fmaf(f.w, f.w, vW))));
        }
    }

    __shared__ float sred[6][TA / 32];
    float vals[6] = { vA, vB, vC, vD, vE, vW };
    #pragma unroll
    for (int c = 0; c < 6; c++) {
        float r = warpSum(vals[c]);
        if ((t & 31) == 0) sred[c][t >> 5] = r;
    }
    __syncthreads();
    if (t < 6) {
        float s = 0.f;
        #pragma unroll
        for (int w = 0; w < TA / 32; w++) s += sred[t][w];
        g_part[((size_t)ii * nb + b) * 6 + t] = s;
    }
}

// ---- S: fold block partials -> coefficients ----------------------------------
__global__ void nebScalars(int nb)
{
    const int j = blockIdx.x;    // interior index
    const int t = threadIdx.x;   // 256

    float acc[6] = {0.f, 0.f, 0.f, 0.f, 0.f, 0.f};
    for (int b = t; b < nb; b += blockDim.x) {
        const float* pp = &g_part[((size_t)j * nb + b) * 6];
        #pragma unroll
        for (int c = 0; c < 6; c++) acc[c] += pp[c];
    }

    __shared__ float sred[6][8];
    #pragma unroll
    for (int c = 0; c < 6; c++) {
        float r = warpSum(acc[c]);
        if ((t & 31) == 0) sred[c][t >> 5] = r;
    }
    __syncthreads();

    if (t == 0) {
        float S[6];
        #pragma unroll
        for (int c = 0; c < 6; c++) {
            float s = 0.f;
            #pragma unroll
            for (int w = 0; w < 8; w++) s += sred[c][w];
            S[c] = s;
        }
        float g1, al, be;
        coefFrom(S, j, g1, al, be);
        g_coef[j * 4 + 0] = g1;
        g_coef[j * 4 + 1] = al;
        g_coef[j * 4 + 2] = be;
    }
}

// ---- O: flat streaming output, REVERSE atom order ------------------------------
// Block b processes the element range of block (G-1-b): first-scheduled blocks
// consume the atom tail that R left resident in L2. Threads ascend -> coalesced.
__global__ void nebOut(
    const float4* __restrict__ pos4,
    const float4* __restrict__ frc4,
    float4* __restrict__ out4,
    int nvec, int n_img)
{
    size_t rb  = (size_t)(gridDim.x - 1u - blockIdx.x);
    size_t gid = rb * blockDim.x + threadIdx.x;
    size_t total = (size_t)n_img * nvec;
    if (gid >= total) return;

    int img = (int)(gid / (unsigned)nvec);
    float4 f = frc4[gid];

    if (img == 0 || img == n_img - 1) { __stcs(&out4[gid], f); return; }

    const int ii = img - 1;
    const float g1 = __ldg(&g_coef[ii * 4 + 0]);
    const float al = __ldg(&g_coef[ii * 4 + 1]);
    const float be = __ldg(&g_coef[ii * 4 + 2]);

    float4 pm = pos4[gid - nvec];
    float4 pc = pos4[gid];
    float4 pp = pos4[gid + nvec];

    float4 o;
    o.x = fmaf(g1, f.x, fmaf(al, pc.x - pm.x, be * (pp.x - pc.x)));
    o.y = fmaf(g1, f.y, fmaf(al, pc.y - pm.y, be * (pp.y - pc.y)));
    o.z = fmaf(g1, f.z, fmaf(al, pc.z - pm.z, be * (pp.z - pc.z)));
    o.w = fmaf(g1, f.w, fmaf(al, pc.w - pm.w, be * (pp.w - pc.w)));
    __stcs(&out4[gid], o);
}

// =============================================================================
extern "C" void kernel_launch(void* const* d_in, const int* in_sizes, int n_in,
                              void* d_out, int out_size)
{
    const float* pos = (const float*)d_in[0];
    const float* frc = (const float*)d_in[1];
    const float* eng = (const float*)d_in[2];

    const int n_img    = in_sizes[2];                 // 32
    const long per_img = (long)in_sizes[0] / n_img;   // 1,200,000 floats
    const int  nvec    = (int)(per_img / 4);          // 300,000 float4
    const int  n_int   = n_img - 2;

    const float4* pos4 = (const float4*)pos;
    const float4* frc4 = (const float4*)frc;
    float4* out4 = (float4*)d_out;

    const int nb = (nvec + TILEA - 1) / TILEA;        // 586 bands

    size_t total = (size_t)n_img * nvec;
    int blocksC = (int)((total + 255) / 256);

    if (n_int < 1) {
        nebOut<<<blocksC, 256>>>(pos4, frc4, out4, nvec, n_img);
        return;
    }

    nebInit<<<1, 32>>>(eng, n_img);
    nebReduceF<<<dim3(n_int, nb), TA>>>(pos4, frc4, nvec, nb);
    nebScalars<<<n_int, 256>>>(nb);
    nebOut<<<blocksC, 256>>>(pos4, frc4, out4, nvec, n_img);
}

// round 10
// speedup vs baseline: 1.0475x; 1.0350x over previous
#include <cuda_runtime.h>
#include <math.h>

// ElasticBand (NEB) — flat 3-pass scheme (R -> S -> O), all passes at the
// achievable DRAM roofline (~6.3 TB/s).
// R: one block per (interior image, atom band); KPT=4 -> 16 independent float4
//    loads per thread, single block reduce, partial -> L2. Image index on
//    blockIdx.x so each wave spans all images for a band: 3x pos reads dedup
//    in L2 (DRAM ~ pos once + frc once).
// S: per-image fold of band partials; eng logic recomputed inline (no init kernel).
// O: flat streaming out = g1*frc + alpha*dp + beta*dm (pos reads L2-deduped).

#define KMAXC 0.1f
#define DLTKC 0.02f
#define EPSC  0.1f
#define PI_F  3.14159265358979323846f

#define TA    256                // threads per block (R)
#define KPT   4                  // float4 per thread (R)
#define TILEA (TA * KPT)         // 1024 float4 per block
#define MAX_INT 62
#define MAX_NB  1280

__device__ float g_part[(size_t)MAX_INT * MAX_NB * 6];  // [ii][band][6]
__device__ float g_coef[MAX_INT * 4];                    // g1, alpha, beta

__device__ __forceinline__ float warpSum(float v) {
    #pragma unroll
    for (int o = 16; o > 0; o >>= 1) v += __shfl_xor_sync(0xffffffffu, v, o);
    return v;
}

__device__ __forceinline__ float spring_k(float ea, float eb, float emax, float eref) {
    float ei = fmaxf(ea, eb);
    float k = KMAXC - DLTKC * (emax - ei) / (emax - eref);
    if (ei < eref) k = KMAXC - DLTKC;
    return k;
}

// ---- R: flat 2D reduce. block = (image ii = blockIdx.x, band b = blockIdx.y) --
__global__ void __launch_bounds__(TA) nebReduceF(
    const float4* __restrict__ pos4,
    const float4* __restrict__ frc4,
    int nvec, int nb)
{
    const int ii = blockIdx.x;        // interior index
    const int i  = ii + 1;            // global image
    const int b  = blockIdx.y;        // atom band
    const int t  = threadIdx.x;

    float vA = 0.f, vB = 0.f, vC = 0.f, vD = 0.f, vE = 0.f, vW = 0.f;

    const int j0 = b * TILEA + t;
    const size_t imgBase = (size_t)i * nvec;

    #pragma unroll
    for (int k = 0; k < KPT; k++) {
        const int j = j0 + k * TA;
        if (j < nvec) {
            const size_t base = imgBase + j;
            float4 pm = pos4[base - nvec];
            float4 pc = pos4[base];
            float4 pp = pos4[base + nvec];
            float4 f  = frc4[base];

            float dpx = pc.x - pm.x, dmx = pp.x - pc.x;
            float dpy = pc.y - pm.y, dmy = pp.y - pc.y;
            float dpz = pc.z - pm.z, dmz = pp.z - pc.z;
            float dpw = pc.w - pm.w, dmw = pp.w - pc.w;

            vA = fmaf(dpx, dpx, fmaf(dpy, dpy, fmaf(dpz, dpz, fmaf(dpw, dpw, vA))));
            vB = fmaf(dmx, dmx, fmaf(dmy, dmy, fmaf(dmz, dmz, fmaf(dmw, dmw, vB))));
            vC = fmaf(dpx, dmx, fmaf(dpy, dmy, fmaf(dpz, dmz, fmaf(dpw, dmw, vC))));
            vD = fmaf(f.x, dpx, fmaf(f.y, dpy, fmaf(f.z, dpz, fmaf(f.w, dpw, vD))));
            vE = fmaf(f.x, dmx, fmaf(f.y, dmy, fmaf(f.z, dmz, fmaf(f.w, dmw, vE))));
            vW = fmaf(f.x, f.x, fmaf(f.y, f.y, fmaf(f.z, f.z, fmaf(f.w, f.w, vW))));
        }
    }

    __shared__ float sred[6][TA / 32];
    float vals[6] = { vA, vB, vC, vD, vE, vW };
    #pragma unroll
    for (int c = 0; c < 6; c++) {
        float r = warpSum(vals[c]);
        if ((t & 31) == 0) sred[c][t >> 5] = r;
    }
    __syncthreads();
    if (t < 6) {
        float s = 0.f;
        #pragma unroll
        for (int w = 0; w < TA / 32; w++) s += sred[t][w];
        g_part[((size_t)ii * nb + b) * 6 + t] = s;
    }
}

// ---- S: fold band partials + inline eng logic -> coefficients -----------------
__global__ void nebScalars(const float* __restrict__ eng, int n_img, int nb)
{
    const int j = blockIdx.x;    // interior index
    const int t = threadIdx.x;   // 256

    float acc[6] = {0.f, 0.f, 0.f, 0.f, 0.f, 0.f};
    for (int b = t; b < nb; b += blockDim.x) {
        const float* pp = &g_part[((size_t)j * nb + b) * 6];
        #pragma unroll
        for (int c = 0; c < 6; c++) acc[c] += pp[c];
    }

    __shared__ float sred[6][8];
    #pragma unroll
    for (int c = 0; c < 6; c++) {
        float r = warpSum(acc[c]);
        if ((t & 31) == 0) sred[c][t >> 5] = r;
    }
    __syncthreads();

    if (t == 0) {
        float S[6];
        #pragma unroll
        for (int c = 0; c < 6; c++) {
            float s = 0.f;
            #pragma unroll
            for (int w = 0; w < 8; w++) s += sred[c][w];
            S[c] = s;
        }
        const float A = S[0], B = S[1], C = S[2], D = S[3], E = S[4], W = S[5];

        // inline eng-derived scalars (32-element scan; trivial)
        float emin = eng[0], emax = eng[0];
        int imax = 0;
        for (int p = 1; p < n_img; p++) {
            float e = eng[p];
            if (e < emin) emin = e;
            if (e > emax) { emax = e; imax = p; }   // strict > keeps first max
        }
        const float eref = emin - EPSC;

        const int i = j + 1;
        const float e0 = eng[i - 1], e1 = eng[i], e2 = eng[i + 1];
        const float km = spring_k(e0, e1, emax, eref);
        const float kp = spring_k(e1, e2, emax, eref);

        float cp, cm;
        if (e2 > e1 && e1 > e0)      { cp = 1.f;  cm = 0.f; }
        else if (e2 < e1 && e1 < e0) { cp = 0.f;  cm = 1.f; }
        else {
            float d1 = fabsf(e2 - e1), d0 = fabsf(e0 - e1);
            float dvmax = fmaxf(d1, d0), dvmin = fminf(d1, d0);
            if (e2 > e1)      { cp = dvmax; cm = dvmin; }
            else if (e2 < e1) { cp = dvmin; cm = dvmax; }
            else              { cp = 0.f;   cm = 0.f; }
        }
        const float mu = (j == imax) ? 2.f : 1.f;   // .at[i_raw] quirk

        const float Stt = cp * cp * A + 2.f * cp * cm * C + cm * cm * B;
        const float Sft = cp * D + cm * E;
        const float a   = Sft / Stt;
        const float s   = (kp * sqrtf(B) - km * sqrtf(A)) / sqrtf(Stt);

        const float F   = W - Sft * Sft / Stt;
        const float Tm  = cp * C + cm * B;
        const float Tp  = cp * A + cm * C;
        const float St  = kp * Tm - km * Tp;
        const float Gv  = kp * kp * B + km * km * A - 2.f * kp * km * C
                          - 2.f * s * St + s * s * Stt;
        const float Sf  = kp * E - km * D;
        const float H   = Sf - a * St - s * Sft + s * a * Stt;

        const float sw  = (2.0f / PI_F) * atan2f(F, Gv);
        const float Hsw = H * sw;

        g_coef[j * 4 + 0] = 1.f - Hsw;
        g_coef[j * 4 + 1] = a * (Hsw - mu) * cp - km;
        g_coef[j * 4 + 2] = a * (Hsw - mu) * cm + kp;
    }
}

// ---- O: flat streaming output (proven 71.9us @ 76.6% DRAM) --------------------
__global__ void nebOut(
    const float4* __restrict__ pos4,
    const float4* __restrict__ frc4,
    float4* __restrict__ out4,
    int nvec, int n_img)
{
    size_t gid = (size_t)blockIdx.x * blockDim.x + threadIdx.x;
    size_t total = (size_t)n_img * nvec;
    if (gid >= total) return;

    int img = (int)(gid / (unsigned)nvec);
    float4 f = frc4[gid];

    if (img == 0 || img == n_img - 1) { out4[gid] = f; return; }

    const int ii = img - 1;
    const float g1 = __ldg(&g_coef[ii * 4 + 0]);
    const float al = __ldg(&g_coef[ii * 4 + 1]);
    const float be = __ldg(&g_coef[ii * 4 + 2]);

    float4 pm = pos4[gid - nvec];
    float4 pc = pos4[gid];
    float4 pp = pos4[gid + nvec];

    float4 o;
    o.x = fmaf(g1, f.x, fmaf(al, pc.x - pm.x, be * (pp.x - pc.x)));
    o.y = fmaf(g1, f.y, fmaf(al, pc.y - pm.y, be * (pp.y - pc.y)));
    o.z = fmaf(g1, f.z, fmaf(al, pc.z - pm.z, be * (pp.z - pc.z)));
    o.w = fmaf(g1, f.w, fmaf(al, pc.w - pm.w, be * (pp.w - pc.w)));
    out4[gid] = o;
}

// =============================================================================
extern "C" void kernel_launch(void* const* d_in, const int* in_sizes, int n_in,
                              void* d_out, int out_size)
{
    const float* pos = (const float*)d_in[0];
    const float* frc = (const float*)d_in[1];
    const float* eng = (const float*)d_in[2];

    const int n_img    = in_sizes[2];                 // 32
    const long per_img = (long)in_sizes[0] / n_img;   // 1,200,000 floats
    const int  nvec    = (int)(per_img / 4);          // 300,000 float4
    const int  n_int   = n_img - 2;

    const float4* pos4 = (const float4*)pos;
    const float4* frc4 = (const float4*)frc;
    float4* out4 = (float4*)d_out;

    const int nb = (nvec + TILEA - 1) / TILEA;        // 293 bands

    size_t total = (size_t)n_img * nvec;
    int blocksC = (int)((total + 255) / 256);

    if (n_int < 1) {
        nebOut<<<blocksC, 256>>>(pos4, frc4, out4, nvec, n_img);
        return;
    }

    nebReduceF<<<dim3(n_int, nb), TA>>>(pos4, frc4, nvec, nb);
    nebScalars<<<n_int, 256>>>(eng, n_img, nb);
    nebOut<<<blocksC, 256>>>(pos4, frc4, out4, nvec, n_img);
}

// round 11
// speedup vs baseline: 1.0501x; 1.0026x over previous
#include <cuda_runtime.h>
#include <math.h>

// ElasticBand (NEB) — flat 3-pass scheme (R -> S -> O) at the DRAM roofline.
// R: one block per (interior image, atom band); KPT=8 -> 32 independent float4
//    loads per thread, ONE block reduce per 2048 float4, partial -> L2.
//    Image on blockIdx.x so each wave spans all images for a band: the 3x pos
//    reads dedup in L2 (DRAM ~ pos once + frc once).
// S: per-image fold of band partials; eng logic recomputed inline.
// O: flat streaming out = g1*frc + alpha*dp + beta*dm (pos reads L2-deduped).

#define KMAXC 0.1f
#define DLTKC 0.02f
#define EPSC  0.1f
#define PI_F  3.14159265358979323846f

#define TA    256                // threads per block (R)
#define KPT   8                  // float4 per thread (R)
#define TILEA (TA * KPT)         // 2048 float4 per block
#define MAX_INT 62
#define MAX_NB  1280

__device__ float g_part[(size_t)MAX_INT * MAX_NB * 6];  // [ii][band][6]
__device__ float g_coef[MAX_INT * 4];                    // g1, alpha, beta

__device__ __forceinline__ float warpSum(float v) {
    #pragma unroll
    for (int o = 16; o > 0; o >>= 1) v += __shfl_xor_sync(0xffffffffu, v, o);
    return v;
}

__device__ __forceinline__ float spring_k(float ea, float eb, float emax, float eref) {
    float ei = fmaxf(ea, eb);
    float k = KMAXC - DLTKC * (emax - ei) / (emax - eref);
    if (ei < eref) k = KMAXC - DLTKC;
    return k;
}

// ---- R: flat 2D reduce. block = (image ii = blockIdx.x, band b = blockIdx.y) --
__global__ void __launch_bounds__(TA) nebReduceF(
    const float4* __restrict__ pos4,
    const float4* __restrict__ frc4,
    int nvec, int nb)
{
    const int ii = blockIdx.x;        // interior index
    const int i  = ii + 1;            // global image
    const int b  = blockIdx.y;        // atom band
    const int t  = threadIdx.x;

    float vA = 0.f, vB = 0.f, vC = 0.f, vD = 0.f, vE = 0.f, vW = 0.f;

    const int j0 = b * TILEA + t;
    const size_t imgBase = (size_t)i * nvec;

    #pragma unroll
    for (int k = 0; k < KPT; k++) {
        const int j = j0 + k * TA;
        if (j < nvec) {
            const size_t base = imgBase + j;
            float4 pm = pos4[base - nvec];
            float4 pc = pos4[base];
            float4 pp = pos4[base + nvec];
            float4 f  = frc4[base];

            float dpx = pc.x - pm.x, dmx = pp.x - pc.x;
            float dpy = pc.y - pm.y, dmy = pp.y - pc.y;
            float dpz = pc.z - pm.z, dmz = pp.z - pc.z;
            float dpw = pc.w - pm.w, dmw = pp.w - pc.w;

            vA = fmaf(dpx, dpx, fmaf(dpy, dpy, fmaf(dpz, dpz, fmaf(dpw, dpw, vA))));
            vB = fmaf(dmx, dmx, fmaf(dmy, dmy, fmaf(dmz, dmz, fmaf(dmw, dmw, vB))));
            vC = fmaf(dpx, dmx, fmaf(dpy, dmy, fmaf(dpz, dmz, fmaf(dpw, dmw, vC))));
            vD = fmaf(f.x, dpx, fmaf(f.y, dpy, fmaf(f.z, dpz, fmaf(f.w, dpw, vD))));
            vE = fmaf(f.x, dmx, fmaf(f.y, dmy, fmaf(f.z, dmz, fmaf(f.w, dmw, vE))));
            vW = fmaf(f.x, f.x, fmaf(f.y, f.y, fmaf(f.z, f.z, fmaf(f.w, f.w, vW))));
        }
    }

    __shared__ float sred[6][TA / 32];
    float vals[6] = { vA, vB, vC, vD, vE, vW };
    #pragma unroll
    for (int c = 0; c < 6; c++) {
        float r = warpSum(vals[c]);
        if ((t & 31) == 0) sred[c][t >> 5] = r;
    }
    __syncthreads();
    if (t < 6) {
        float s = 0.f;
        #pragma unroll
        for (int w = 0; w < TA / 32; w++) s += sred[t][w];
        g_part[((size_t)ii * nb + b) * 6 + t] = s;
    }
}

// ---- S: fold band partials + inline eng logic -> coefficients -----------------
__global__ void nebScalars(const float* __restrict__ eng, int n_img, int nb)
{
    const int j = blockIdx.x;    // interior index
    const int t = threadIdx.x;   // 256

    float acc[6] = {0.f, 0.f, 0.f, 0.f, 0.f, 0.f};
    for (int b = t; b < nb; b += blockDim.x) {
        const float* pp = &g_part[((size_t)j * nb + b) * 6];
        #pragma unroll
        for (int c = 0; c < 6; c++) acc[c] += pp[c];
    }

    __shared__ float sred[6][8];
    #pragma unroll
    for (int c = 0; c < 6; c++) {
        float r = warpSum(acc[c]);
        if ((t & 31) == 0) sred[c][t >> 5] = r;
    }
    __syncthreads();

    if (t == 0) {
        float S[6];
        #pragma unroll
        for (int c = 0; c < 6; c++) {
            float s = 0.f;
            #pragma unroll
            for (int w = 0; w < 8; w++) s += sred[c][w];
            S[c] = s;
        }
        const float A = S[0], B = S[1], C = S[2], D = S[3], E = S[4], W = S[5];

        // inline eng-derived scalars (32-element scan; trivial)
        float emin = eng[0], emax = eng[0];
        int imax = 0;
        for (int p = 1; p < n_img; p++) {
            float e = eng[p];
            if (e < emin) emin = e;
            if (e > emax) { emax = e; imax = p; }   // strict > keeps first max
        }
        const float eref = emin - EPSC;

        const int i = j + 1;
        const float e0 = eng[i - 1], e1 = eng[i], e2 = eng[i + 1];
        const float km = spring_k(e0, e1, emax, eref);
        const float kp = spring_k(e1, e2, emax, eref);

        float cp, cm;
        if (e2 > e1 && e1 > e0)      { cp = 1.f;  cm = 0.f; }
        else if (e2 < e1 && e1 < e0) { cp = 0.f;  cm = 1.f; }
        else {
            float d1 = fabsf(e2 - e1), d0 = fabsf(e0 - e1);
            float dvmax = fmaxf(d1, d0), dvmin = fminf(d1, d0);
            if (e2 > e1)      { cp = dvmax; cm = dvmin; }
            else if (e2 < e1) { cp = dvmin; cm = dvmax; }
            else              { cp = 0.f;   cm = 0.f; }
        }
        const float mu = (j == imax) ? 2.f : 1.f;   // .at[i_raw] quirk

        const float Stt = cp * cp * A + 2.f * cp * cm * C + cm * cm * B;
        const float Sft = cp * D + cm * E;
        const float a   = Sft / Stt;
        const float s   = (kp * sqrtf(B) - km * sqrtf(A)) / sqrtf(Stt);

        const float F   = W - Sft * Sft / Stt;
        const float Tm  = cp * C + cm * B;
        const float Tp  = cp * A + cm * C;
        const float St  = kp * Tm - km * Tp;
        const float Gv  = kp * kp * B + km * km * A - 2.f * kp * km * C
                          - 2.f * s * St + s * s * Stt;
        const float Sf  = kp * E - km * D;
        const float H   = Sf - a * St - s * Sft + s * a * Stt;

        const float sw  = (2.0f / PI_F) * atan2f(F, Gv);
        const float Hsw = H * sw;

        g_coef[j * 4 + 0] = 1.f - Hsw;
        g_coef[j * 4 + 1] = a * (Hsw - mu) * cp - km;
        g_coef[j * 4 + 2] = a * (Hsw - mu) * cm + kp;
    }
}

// ---- O: flat streaming output (proven 71.9us @ 76.6% DRAM) --------------------
__global__ void nebOut(
    const float4* __restrict__ pos4,
    const float4* __restrict__ frc4,
    float4* __restrict__ out4,
    int nvec, int n_img)
{
    size_t gid = (size_t)blockIdx.x * blockDim.x + threadIdx.x;
    size_t total = (size_t)n_img * nvec;
    if (gid >= total) return;

    int img = (int)(gid / (unsigned)nvec);
    float4 f = frc4[gid];

    if (img == 0 || img == n_img - 1) { out4[gid] = f; return; }

    const int ii = img - 1;
    const float g1 = __ldg(&g_coef[ii * 4 + 0]);
    const float al = __ldg(&g_coef[ii * 4 + 1]);
    const float be = __ldg(&g_coef[ii * 4 + 2]);

    float4 pm = pos4[gid - nvec];
    float4 pc = pos4[gid];
    float4 pp = pos4[gid + nvec];

    float4 o;
    o.x = fmaf(g1, f.x, fmaf(al, pc.x - pm.x, be * (pp.x - pc.x)));
    o.y = fmaf(g1, f.y, fmaf(al, pc.y - pm.y, be * (pp.y - pc.y)));
    o.z = fmaf(g1, f.z, fmaf(al, pc.z - pm.z, be * (pp.z - pc.z)));
    o.w = fmaf(g1, f.w, fmaf(al, pc.w - pm.w, be * (pp.w - pc.w)));
    out4[gid] = o;
}

// =============================================================================
extern "C" void kernel_launch(void* const* d_in, const int* in_sizes, int n_in,
                              void* d_out, int out_size)
{
    const float* pos = (const float*)d_in[0];
    const float* frc = (const float*)d_in[1];
    const float* eng = (const float*)d_in[2];

    const int n_img    = in_sizes[2];                 // 32
    const long per_img = (long)in_sizes[0] / n_img;   // 1,200,000 floats
    const int  nvec    = (int)(per_img / 4);          // 300,000 float4
    const int  n_int   = n_img - 2;

    const float4* pos4 = (const float4*)pos;
    const float4* frc4 = (const float4*)frc;
    float4* out4 = (float4*)d_out;

    const int nb = (nvec + TILEA - 1) / TILEA;        // 147 bands

    size_t total = (size_t)n_img * nvec;
    int blocksC = (int)((total + 255) / 256);

    if (n_int < 1) {
        nebOut<<<blocksC, 256>>>(pos4, frc4, out4, nvec, n_img);
        return;
    }

    nebReduceF<<<dim3(n_int, nb), TA>>>(pos4, frc4, nvec, nb);
    nebScalars<<<n_int, 256>>>(eng, n_img, nb);
    nebOut<<<blocksC, 256>>>(pos4, frc4, out4, nvec, n_img);
}